// round 8
// baseline (speedup 1.0000x reference)
#include <cuda_runtime.h>

// AvgPool2d 64x64, stride 1, replicate edge-pad. x: (16,64,256,256) fp32.
// One CTA per image. WARP-SPECIALIZED: warps 0-7 produce horizontal 64-window
// sums (2 rows each per 16-row batch, register-only scan+shuffle) into a
// 96-row smem ring; warps 8-15 (256 threads, one output column each) consume
// via vertical sliding 64-window and write coalesced rows. Producer/consumer
// handoff via named barriers: FULL(3,4) producer-arrive/consumer-sync,
// EMPTY(1,2) consumer-arrive/producer-sync (producers run <=2 batches ahead;
// ring slot disjointness verified for that lead). 75 KB smem -> 2 CTAs/SM.

#define IMG_ELEMS 65536        // 256*256
#define HSTR 196               // float4-aligned H rows
#define RING 96                // 6 batches of 16 rows
#define SMEM_BYTES (RING * HSTR * 4)   // 75264 B

#define BAR_ARRIVE(id) asm volatile("bar.arrive %0, 512;" :: "r"(id) : "memory")
#define BAR_SYNC(id)   asm volatile("bar.sync %0, 512;"   :: "r"(id) : "memory")

__device__ __forceinline__ void scan_store(float4 va, float4 vb,
                                           float* Hrow, int lane) {
    // local inclusive prefix over this lane's 8 values
    float p0 = va.x;
    float p1 = p0 + va.y;
    float p2 = p1 + va.z;
    float p3 = p2 + va.w;
    float p4 = p3 + vb.x;
    float p5 = p4 + vb.y;
    float p6 = p5 + vb.z;
    float p7 = p6 + vb.w;

    // warp inclusive scan of lane totals
    float t = p7;
    #pragma unroll
    for (int o = 1; o < 32; o <<= 1) {
        float u = __shfl_up_sync(0xffffffffu, t, o);
        if (lane >= o) t += u;
    }
    const float e = t - p7;                   // global prefix at 8*lane-1

    p0 += e; p1 += e; p2 += e; p3 += e;
    p4 += e; p5 += e; p6 += e; p7 += e;

    // H[8l] = q7(lane l+7) - e ; H[8l+k] = q_{k-1}(lane l+8) - q_{k-1}
    // lane 24's h0 = H[192].
    float s7 = __shfl_down_sync(0xffffffffu, p7, 7);
    float s0 = __shfl_down_sync(0xffffffffu, p0, 8);
    float s1 = __shfl_down_sync(0xffffffffu, p1, 8);
    float s2 = __shfl_down_sync(0xffffffffu, p2, 8);
    float s3 = __shfl_down_sync(0xffffffffu, p3, 8);
    float s4 = __shfl_down_sync(0xffffffffu, p4, 8);
    float s5 = __shfl_down_sync(0xffffffffu, p5, 8);
    float s6 = __shfl_down_sync(0xffffffffu, p6, 8);

    if (lane < 24) {
        float4 v0 = make_float4(s7 - e,  s0 - p0, s1 - p1, s2 - p2);
        float4 v1 = make_float4(s3 - p3, s4 - p4, s5 - p5, s6 - p6);
        float4* hp = (float4*)(Hrow + 8 * lane);
        hp[0] = v0;
        hp[1] = v1;
    } else if (lane == 24) {
        Hrow[192] = s7 - e;
    }
}

__global__ __launch_bounds__(512, 2)
void avgpool64_ws(const float* __restrict__ x, float* __restrict__ out) {
    extern __shared__ float Hs[];                 // [RING][HSTR]

    const int tid  = threadIdx.x;
    const int wid  = tid >> 5;
    const int lane = tid & 31;

    const float* img    = x   + (size_t)blockIdx.x * IMG_ELEMS;
    float*       outImg = out + (size_t)blockIdx.x * IMG_ELEMS;

    if (wid < 8) {
        // ======================= PRODUCERS =======================
        // warp w: rows 16bt + w and 16bt + w + 8
        const float4* rp = (const float4*)img + lane * 2;
        float4 a  = __ldcs(rp + wid * 64);
        float4 b  = __ldcs(rp + wid * 64 + 1);
        float4 a2 = __ldcs(rp + (wid + 8) * 64);
        float4 b2 = __ldcs(rp + (wid + 8) * 64 + 1);

        int base = 0;                             // (16*bt) % RING
        #pragma unroll 1
        for (int bt = 0; bt < 16; ++bt) {
            const int r = bt * 16 + wid;

            float4 ca = a, cb = b, ca2 = a2, cb2 = b2;
            if (bt < 15) {                        // prefetch next batch
                a  = __ldcs(rp + (r + 16) * 64);
                b  = __ldcs(rp + (r + 16) * 64 + 1);
                a2 = __ldcs(rp + (r + 24) * 64);
                b2 = __ldcs(rp + (r + 24) * 64 + 1);
            }

            if (bt >= 2) BAR_SYNC(1 + (bt & 1)); // consumer freed bt-2's slots

            scan_store(ca,  cb,  Hs + (base + wid)     * HSTR, lane);
            scan_store(ca2, cb2, Hs + (base + wid + 8) * HSTR, lane);

            BAR_ARRIVE(3 + (bt & 1));            // batch bt full

            base += 16;
            if (base >= RING) base -= RING;
        }
    } else {
        // ======================= CONSUMERS =======================
        const int j = tid & 255;                  // output column
        int cj = j - 31;
        cj = cj < 0 ? 0 : (cj > 192 ? 192 : cj);
        const float* Hcj = Hs + cj;
        float vs = 0.0f;
        const float inv = 1.0f / 4096.0f;

        int base = 0;
        #pragma unroll 1
        for (int ct = 0; ct < 16; ++ct) {
            BAR_SYNC(3 + (ct & 1));               // batch ct full

            const float* Hn = Hcj + base * HSTR;  // rows 16ct+k
            int sob = base + 32;                  // rows 16ct+k-64
            if (sob >= RING) sob -= RING;
            const float* Ho = Hcj + sob * HSTR;
            float* op = outImg + ((ct * 16 - 32) * 256 + j);

            if (ct < 4) {                         // warmup rows 0..63
                #pragma unroll
                for (int k = 0; k < 16; ++k)
                    vs += Hn[k * HSTR];
                if (ct == 3) {                    // box[0] -> y 0..31
                    float v = vs * inv;
                    #pragma unroll
                    for (int y = 0; y < 32; ++y)
                        __stcs(outImg + (y * 256 + j), v);
                }
            } else {                              // boxes 16ct-63 .. 16ct-48... slide
                #pragma unroll
                for (int k = 0; k < 16; ++k) {
                    vs += Hn[k * HSTR] - Ho[k * HSTR];
                    __stcs(op + k * 256, vs * inv);   // y = 16ct-32+k
                }
                if (ct == 15) {                   // box[192] -> y 224..255
                    float v = vs * inv;
                    #pragma unroll
                    for (int y = 224; y < 256; ++y)
                        __stcs(outImg + (y * 256 + j), v);
                }
            }

            BAR_ARRIVE(1 + (ct & 1));             // batch ct's old slots free

            base += 16;
            if (base >= RING) base -= RING;
        }
    }
}

extern "C" void kernel_launch(void* const* d_in, const int* in_sizes, int n_in,
                              void* d_out, int out_size) {
    const float* x = (const float*)d_in[0];
    float* out = (float*)d_out;
    const int n_images = in_sizes[0] / IMG_ELEMS;   // 16*64 = 1024

    cudaFuncSetAttribute(avgpool64_ws,
                         cudaFuncAttributeMaxDynamicSharedMemorySize, SMEM_BYTES);
    avgpool64_ws<<<n_images, 512, SMEM_BYTES>>>(x, out);
}

// round 9
// speedup vs baseline: 1.0822x; 1.0822x over previous
#include <cuda_runtime.h>

// AvgPool2d 64x64, stride 1, replicate edge-pad. x: (16,64,256,256) fp32.
// v4 pipeline (16-row batches, register-only horizontal scan, 96-row smem
// ring, one __syncthreads/batch, split vertical pass) + TAIL SHAPING:
// first n_full CTAs (3 exact waves = 888 at 2 CTAs/SM on 148 SMs) process one
// full image each; the last 136 images are split into 272 half-image CTAs
// (~0.56x duration, 1.25x input reads) that form a short final wave.

#define IMG_ELEMS 65536        // 256*256
#define HSTR 196               // float4-aligned H rows
#define RING 96                // 64-row window + 16-row batch + 16 slack
#define SMEM_BYTES (RING * HSTR * 4)   // 75264 B -> 2 CTAs/SM

__device__ __forceinline__ void scan_store(float4 va, float4 vb,
                                           float* Hrow, int lane) {
    float p0 = va.x;
    float p1 = p0 + va.y;
    float p2 = p1 + va.z;
    float p3 = p2 + va.w;
    float p4 = p3 + vb.x;
    float p5 = p4 + vb.y;
    float p6 = p5 + vb.z;
    float p7 = p6 + vb.w;

    float t = p7;
    #pragma unroll
    for (int o = 1; o < 32; o <<= 1) {
        float u = __shfl_up_sync(0xffffffffu, t, o);
        if (lane >= o) t += u;
    }
    const float e = t - p7;                   // global prefix at 8*lane-1

    p0 += e; p1 += e; p2 += e; p3 += e;
    p4 += e; p5 += e; p6 += e; p7 += e;

    // H[8l] = q7(lane l+7) - e ; H[8l+k] = q_{k-1}(lane l+8) - q_{k-1}
    float s7 = __shfl_down_sync(0xffffffffu, p7, 7);
    float s0 = __shfl_down_sync(0xffffffffu, p0, 8);
    float s1 = __shfl_down_sync(0xffffffffu, p1, 8);
    float s2 = __shfl_down_sync(0xffffffffu, p2, 8);
    float s3 = __shfl_down_sync(0xffffffffu, p3, 8);
    float s4 = __shfl_down_sync(0xffffffffu, p4, 8);
    float s5 = __shfl_down_sync(0xffffffffu, p5, 8);
    float s6 = __shfl_down_sync(0xffffffffu, p6, 8);

    if (lane < 24) {
        float4 v0 = make_float4(s7 - e,  s0 - p0, s1 - p1, s2 - p2);
        float4 v1 = make_float4(s3 - p3, s4 - p4, s5 - p5, s6 - p6);
        float4* hp = (float4*)(Hrow + 8 * lane);
        hp[0] = v0;
        hp[1] = v1;
    } else if (lane == 24) {
        Hrow[192] = s7 - e;
    }
}

// ---------------- full image: exact v4 body ----------------
__device__ void run_full(const float* __restrict__ img,
                         float* __restrict__ outImg,
                         float* Hs, int tid, int wid, int lane) {
    const int g = tid >> 8;
    const int j = tid & 255;
    int cj = j - 31;
    cj = cj < 0 ? 0 : (cj > 192 ? 192 : cj);
    const float* Hcj = Hs + cj;
    float vs = 0.0f;
    const float inv = 1.0f / 4096.0f;

    const float4* rp = (const float4*)img + lane * 2;
    float4 a = __ldcs(rp + wid * 64);
    float4 b = __ldcs(rp + wid * 64 + 1);

    int base = 0;
    #pragma unroll 1
    for (int bt = 0; bt < 16; ++bt) {
        const int r = bt * 16 + wid;
        float4 ca = a, cb = b;
        if (bt < 15) {
            a = __ldcs(rp + (r + 16) * 64);
            b = __ldcs(rp + (r + 16) * 64 + 1);
        }
        scan_store(ca, cb, Hs + (base + wid) * HSTR, lane);

        __syncthreads();

        {
            const float* Hn = Hcj + base * HSTR;
            int sob = base + 32;
            if (sob >= RING) sob -= RING;
            const float* Ho = Hcj + sob * HSTR;
            float* op = outImg + ((bt * 16 - 32) * 256 + j);

            if (g == 0) {
                if (bt < 4) {
                    #pragma unroll
                    for (int k = 0; k < 16; ++k) vs += Hn[k * HSTR];
                    if (bt == 3) {
                        float v = vs * inv;
                        #pragma unroll
                        for (int y = 0; y < 32; ++y)
                            __stcs(outImg + (y * 256 + j), v);
                    }
                } else if (bt <= 9) {
                    #pragma unroll
                    for (int k = 0; k < 16; ++k) {
                        vs += Hn[k * HSTR] - Ho[k * HSTR];
                        __stcs(op + k * 256, vs * inv);
                    }
                }
            } else {
                if (bt >= 6 && bt < 10) {
                    if (bt == 6) {
                        #pragma unroll
                        for (int k = 1; k < 16; ++k) vs += Hn[k * HSTR];
                    } else {
                        #pragma unroll
                        for (int k = 0; k < 16; ++k) vs += Hn[k * HSTR];
                    }
                } else if (bt == 10) {
                    vs += Hn[0];
                    __stcs(op, vs * inv);                 // y = 128
                    #pragma unroll
                    for (int k = 1; k < 16; ++k) {
                        vs += Hn[k * HSTR] - Ho[k * HSTR];
                        __stcs(op + k * 256, vs * inv);
                    }
                } else if (bt >= 11) {
                    #pragma unroll
                    for (int k = 0; k < 16; ++k) {
                        vs += Hn[k * HSTR] - Ho[k * HSTR];
                        __stcs(op + k * 256, vs * inv);
                    }
                    if (bt == 15) {
                        float v = vs * inv;
                        #pragma unroll
                        for (int y = 224; y < 256; ++y)
                            __stcs(outImg + (y * 256 + j), v);
                    }
                }
            }
        }

        base += 16;
        if (base >= RING) base -= RING;
    }
}

// ---------------- half image (h=0 top: y 0..127, rows 0..159;
//                  h=1 bottom: y 128..255, rows 96..255) ----------------
__device__ void run_half(const float* __restrict__ img,
                         float* __restrict__ outImg, int h,
                         float* Hs, int tid, int wid, int lane) {
    const int row0 = h ? 96 : 0;                  // first input row
    const int j = tid & 255;
    int cj = j - 31;
    cj = cj < 0 ? 0 : (cj > 192 ? 192 : cj);
    const float* Hcj = Hs + cj;
    float vs = 0.0f;
    const float inv = 1.0f / 4096.0f;

    const float4* rp = (const float4*)(img + row0 * 256) + lane * 2;
    float4 a = __ldcs(rp + wid * 64);
    float4 b = __ldcs(rp + wid * 64 + 1);

    int base = 0;
    #pragma unroll 1
    for (int bt = 0; bt < 10; ++bt) {             // 160 local rows
        const int r = bt * 16 + wid;              // local row
        float4 ca = a, cb = b;
        if (bt < 9) {
            a = __ldcs(rp + (r + 16) * 64);
            b = __ldcs(rp + (r + 16) * 64 + 1);
        }
        scan_store(ca, cb, Hs + (base + wid) * HSTR, lane);

        __syncthreads();

        if (tid < 256) {
            const float* Hn = Hcj + base * HSTR;  // local rows 16bt+k
            int sob = base + 32;
            if (sob >= RING) sob -= RING;
            const float* Ho = Hcj + sob * HSTR;   // local rows 16bt+k-64

            if (h == 0) {                         // boxes 0..96, y 0..127
                float* op = outImg + ((bt * 16 - 32) * 256 + j);
                if (bt < 4) {
                    #pragma unroll
                    for (int k = 0; k < 16; ++k) vs += Hn[k * HSTR];
                    if (bt == 3) {                // box[0] -> y 0..31
                        float v = vs * inv;
                        #pragma unroll
                        for (int y = 0; y < 32; ++y)
                            __stcs(outImg + (y * 256 + j), v);
                    }
                } else {                          // bt 4..9 -> y 32..127
                    #pragma unroll
                    for (int k = 0; k < 16; ++k) {
                        vs += Hn[k * HSTR] - Ho[k * HSTR];
                        __stcs(op + k * 256, vs * inv);
                    }
                }
            } else {                              // boxes 97..192, y 128..255
                float* op = outImg + ((bt * 16 + 64) * 256 + j);
                if (bt == 0) {
                    #pragma unroll
                    for (int k = 1; k < 16; ++k)  // local rows 1..15
                        vs += Hn[k * HSTR];
                } else if (bt < 4) {
                    #pragma unroll
                    for (int k = 0; k < 16; ++k)  // local rows ..63
                        vs += Hn[k * HSTR];
                } else if (bt == 4) {
                    vs += Hn[0];                  // local row 64 -> box 97
                    __stcs(op, vs * inv);         // y = 128
                    #pragma unroll
                    for (int k = 1; k < 16; ++k) {
                        vs += Hn[k * HSTR] - Ho[k * HSTR];
                        __stcs(op + k * 256, vs * inv);   // y = 128+k
                    }
                } else {                          // bt 5..9 -> y 144..223
                    #pragma unroll
                    for (int k = 0; k < 16; ++k) {
                        vs += Hn[k * HSTR] - Ho[k * HSTR];
                        __stcs(op + k * 256, vs * inv);
                    }
                    if (bt == 9) {                // box[192] -> y 224..255
                        float v = vs * inv;
                        #pragma unroll
                        for (int y = 224; y < 256; ++y)
                            __stcs(outImg + (y * 256 + j), v);
                    }
                }
            }
        }

        base += 16;
        if (base >= RING) base -= RING;
    }
}

__global__ __launch_bounds__(512, 2)
void avgpool64_v7(const float* __restrict__ x, float* __restrict__ out,
                  int n_full) {
    extern __shared__ float Hs[];
    const int tid  = threadIdx.x;
    const int wid  = tid >> 5;
    const int lane = tid & 31;
    const int bid  = blockIdx.x;

    if (bid < n_full) {
        const float* img = x   + (size_t)bid * IMG_ELEMS;
        float*       o   = out + (size_t)bid * IMG_ELEMS;
        run_full(img, o, Hs, tid, wid, lane);
    } else {
        const int u   = bid - n_full;
        const int im  = n_full + (u >> 1);
        const int h   = u & 1;
        const float* img = x   + (size_t)im * IMG_ELEMS;
        float*       o   = out + (size_t)im * IMG_ELEMS;
        run_half(img, o, h, Hs, tid, wid, lane);
    }
}

extern "C" void kernel_launch(void* const* d_in, const int* in_sizes, int n_in,
                              void* d_out, int out_size) {
    const float* x = (const float*)d_in[0];
    float* out = (float*)d_out;
    const int n_images = in_sizes[0] / IMG_ELEMS;   // 16*64 = 1024

    // 3 exact waves of full-image CTAs (148 SMs x 2 CTAs x 3), remainder split
    // into half-image CTAs that form a short final wave.
    int n_full, grid;
    const int three_waves = 148 * 2 * 3;            // 888
    if (n_images > three_waves) {
        n_full = three_waves;
        grid   = n_full + 2 * (n_images - n_full);  // 888 + 272 = 1160
    } else {
        n_full = n_images;
        grid   = n_images;
    }

    cudaFuncSetAttribute(avgpool64_v7,
                         cudaFuncAttributeMaxDynamicSharedMemorySize, SMEM_BYTES);
    avgpool64_v7<<<grid, 512, SMEM_BYTES>>>(x, out, n_full);
}